// round 3
// baseline (speedup 1.0000x reference)
#include <cuda_runtime.h>
#include <math.h>

#define TM 128
#define TN 64
#define TK 32
#define NTHREADS 256
#define D_DIM 1280

// Shared memory plan (union, 8576 floats = 34.3 KB static):
//   GEMM phase : xs = smem[0 .. 128*32)          (x tile, [row][k])
//                ws = smem[4096 .. 4096+32*64)   (W1 tile, [k][n])
//   Epi phase  : hs = smem[0 .. 128*65)          (h tile, [row][n], pad 65)
//                w2s = smem[8320 .. 8320+256)    (W2, [4][64])
__global__ __launch_bounds__(NTHREADS)
void fused_qh_kernel(const float* __restrict__ x,
                     const float* __restrict__ W1,
                     const float* __restrict__ b1,
                     const float* __restrict__ bn_g,
                     const float* __restrict__ bn_b,
                     const float* __restrict__ bn_m,
                     const float* __restrict__ bn_v,
                     const float* __restrict__ W2,
                     const float* __restrict__ b2,
                     const float* __restrict__ qw,
                     const float* __restrict__ W3,
                     const float* __restrict__ b3,
                     float* __restrict__ out,
                     int B)
{
    __shared__ float smem[TM * 65 + 256];

    const int tid = threadIdx.x;
    const int tx = tid & 15;       // 16 column-groups of 4
    const int ty = tid >> 4;       // 16 row-groups of 8
    const int row0 = blockIdx.x * TM;

    float acc[8][4];
#pragma unroll
    for (int i = 0; i < 8; i++) {
        acc[i][0] = 0.f; acc[i][1] = 0.f; acc[i][2] = 0.f; acc[i][3] = 0.f;
    }

    float4 xbuf[4], wbuf[2];

    // Prologue: load first K tile (k0 = 0) into registers
#pragma unroll
    for (int it = 0; it < 4; ++it) {
        int f = tid + it * NTHREADS;
        int r = f >> 3, kq = f & 7;
        int gr = row0 + r;
        xbuf[it] = make_float4(0.f, 0.f, 0.f, 0.f);
        if (gr < B)
            xbuf[it] = *(const float4*)(x + (size_t)gr * D_DIM + kq * 4);
    }
#pragma unroll
    for (int it = 0; it < 2; ++it) {
        int f = tid + it * NTHREADS;
        int n = f >> 3, kq = f & 7;
        wbuf[it] = *(const float4*)(W1 + (size_t)n * D_DIM + kq * 4);
    }

    // ---------------- GEMM1: h = x @ W1^T  (K loop, reg-prefetch pipelined) ----
    for (int k0 = 0; k0 < D_DIM; k0 += TK) {
        // Commit prefetched registers to smem
#pragma unroll
        for (int it = 0; it < 4; ++it) {
            int f = tid + it * NTHREADS;
            int r = f >> 3, kq = f & 7;
            *(float4*)&smem[r * TK + kq * 4] = xbuf[it];
        }
#pragma unroll
        for (int it = 0; it < 2; ++it) {
            int f = tid + it * NTHREADS;
            int n = f >> 3, kq = f & 7;
            float4 v = wbuf[it];
            smem[TM * TK + (kq * 4 + 0) * TN + n] = v.x;
            smem[TM * TK + (kq * 4 + 1) * TN + n] = v.y;
            smem[TM * TK + (kq * 4 + 2) * TN + n] = v.z;
            smem[TM * TK + (kq * 4 + 3) * TN + n] = v.w;
        }
        __syncthreads();

        // Issue next-tile global loads early (overlap with FFMA loop below)
        int k1 = k0 + TK;
        if (k1 < D_DIM) {
#pragma unroll
            for (int it = 0; it < 4; ++it) {
                int f = tid + it * NTHREADS;
                int r = f >> 3, kq = f & 7;
                int gr = row0 + r;
                xbuf[it] = make_float4(0.f, 0.f, 0.f, 0.f);
                if (gr < B)
                    xbuf[it] = *(const float4*)(x + (size_t)gr * D_DIM + k1 + kq * 4);
            }
#pragma unroll
            for (int it = 0; it < 2; ++it) {
                int f = tid + it * NTHREADS;
                int n = f >> 3, kq = f & 7;
                wbuf[it] = *(const float4*)(W1 + (size_t)n * D_DIM + k1 + kq * 4);
            }
        }

#pragma unroll
        for (int k = 0; k < TK; k++) {
            float4 wv = *(const float4*)&smem[TM * TK + k * TN + tx * 4];
#pragma unroll
            for (int i = 0; i < 8; i++) {
                float a = smem[(ty * 8 + i) * TK + k];
                acc[i][0] = fmaf(a, wv.x, acc[i][0]);
                acc[i][1] = fmaf(a, wv.y, acc[i][1]);
                acc[i][2] = fmaf(a, wv.z, acc[i][2]);
                acc[i][3] = fmaf(a, wv.w, acc[i][3]);
            }
        }
        __syncthreads();
    }

    // ---------------- bias + relu + BN affine -> hs in smem ----------------
    {
        int c0 = tx * 4;
#pragma unroll
        for (int j = 0; j < 4; j++) {
            int c = c0 + j;
            float S = bn_g[c] * rsqrtf(bn_v[c] + 1e-5f);
            float T = bn_b[c] - bn_m[c] * S;
            float bb = b1[c];
#pragma unroll
            for (int i = 0; i < 8; i++) {
                float h = acc[i][j] + bb;
                h = fmaxf(h, 0.f);
                smem[(ty * 8 + i) * 65 + c] = fmaf(h, S, T);
            }
        }
    }
    // stage W2 (4x64) into smem
    smem[TM * 65 + tid] = W2[tid];
    __syncthreads();

    // ---------------- per-row epilogue: GEMM2 + quantum circuit ----------------
    if (tid < TM) {
        int row = row0 + tid;
        if (row < B) {
            const float* w2s = &smem[TM * 65];
            float xq0 = b2[0], xq1 = b2[1], xq2 = b2[2], xq3 = b2[3];
#pragma unroll
            for (int n = 0; n < 64; n++) {
                float h = smem[tid * 65 + n];
                xq0 = fmaf(h, w2s[n], xq0);
                xq1 = fmaf(h, w2s[64 + n], xq1);
                xq2 = fmaf(h, w2s[128 + n], xq2);
                xq3 = fmaf(h, w2s[192 + n], xq3);
            }
            // xq = tanh(h@W2+b2); angles = tanh(xq) * pi   (double tanh per reference)
            float xq[4] = { tanhf(xq0), tanhf(xq1), tanhf(xq2), tanhf(xq3) };
            float cc[4], ss[4];
#pragma unroll
            for (int i = 0; i < 4; i++) {
                float a = tanhf(xq[i]) * 3.14159274101257324f;
                sincosf(0.5f * a, &ss[i], &cc[i]);
            }
            // initial product state after per-wire RY on |0000>
            // wire 0 = MSB (bit 8), wire 3 = LSB (bit 1)
            float re[16], im[16];
#pragma unroll
            for (int idx = 0; idx < 16; ++idx) {
                re[idx] = ((idx & 8) ? ss[0] : cc[0]) * ((idx & 4) ? ss[1] : cc[1]) *
                          ((idx & 2) ? ss[2] : cc[2]) * ((idx & 1) ? ss[3] : cc[3]);
                im[idx] = 0.f;
            }
            // layers: per wire RY(qw[l,i,0]) then RZ(qw[l,i,1]), then CNOT ring
#pragma unroll
            for (int l = 0; l < 2; l++) {
#pragma unroll
                for (int i = 0; i < 4; i++) {
                    float thy = qw[l * 8 + i * 2 + 0];
                    float thz = qw[l * 8 + i * 2 + 1];
                    float cy, sy, cz, sz;
                    sincosf(0.5f * thy, &sy, &cy);
                    sincosf(0.5f * thz, &sz, &cz);
                    int mask = 8 >> i;
#pragma unroll
                    for (int idx = 0; idx < 16; ++idx) {
                        if (idx & mask) continue;
                        int p = idx | mask;
                        float r0 = re[idx], i0 = im[idx], r1 = re[p], i1 = im[p];
                        // RY
                        float nr0 = cy * r0 - sy * r1, ni0 = cy * i0 - sy * i1;
                        float nr1 = sy * r0 + cy * r1, ni1 = sy * i0 + cy * i1;
                        // RZ: a0 *= (cz - i sz); a1 *= (cz + i sz)
                        re[idx] = fmaf(sz, ni0, cz * nr0);
                        im[idx] = fmaf(-sz, nr0, cz * ni0);
                        re[p]   = fmaf(-sz, ni1, cz * nr1);
                        im[p]   = fmaf(sz, nr1, cz * ni1);
                    }
                }
                // CNOT ring: (0->1)(1->2)(2->3)(3->0)
#pragma unroll
                for (int i = 0; i < 4; i++) {
                    int mc = 8 >> i, mt = 8 >> ((i + 1) & 3);
#pragma unroll
                    for (int idx = 0; idx < 16; ++idx) {
                        if ((idx & mc) && !(idx & mt)) {
                            int p = idx | mt;
                            float t;
                            t = re[idx]; re[idx] = re[p]; re[p] = t;
                            t = im[idx]; im[idx] = im[p]; im[p] = t;
                        }
                    }
                }
            }
            // <Z_i> expectations
            float z0 = 0.f, z1 = 0.f, z2 = 0.f, z3 = 0.f;
#pragma unroll
            for (int idx = 0; idx < 16; ++idx) {
                float p = re[idx] * re[idx] + im[idx] * im[idx];
                z0 += (idx & 8) ? -p : p;
                z1 += (idx & 4) ? -p : p;
                z2 += (idx & 2) ? -p : p;
                z3 += (idx & 1) ? -p : p;
            }
            // final linear: out = z @ W3^T + b3
#pragma unroll
            for (int c = 0; c < 10; c++) {
                float o = b3[c];
                o = fmaf(z0, W3[c * 4 + 0], o);
                o = fmaf(z1, W3[c * 4 + 1], o);
                o = fmaf(z2, W3[c * 4 + 2], o);
                o = fmaf(z3, W3[c * 4 + 3], o);
                out[(size_t)row * 10 + c] = o;
            }
        }
    }
}

extern "C" void kernel_launch(void* const* d_in, const int* in_sizes, int n_in,
                              void* d_out, int out_size)
{
    const float* x    = (const float*)d_in[0];
    const float* W1   = (const float*)d_in[1];
    const float* b1   = (const float*)d_in[2];
    const float* bn_g = (const float*)d_in[3];
    const float* bn_b = (const float*)d_in[4];
    const float* bn_m = (const float*)d_in[5];
    const float* bn_v = (const float*)d_in[6];
    const float* W2   = (const float*)d_in[7];
    const float* b2   = (const float*)d_in[8];
    const float* qw   = (const float*)d_in[9];
    const float* W3   = (const float*)d_in[10];
    const float* b3   = (const float*)d_in[11];
    float* out = (float*)d_out;

    int B = in_sizes[0] / D_DIM;
    int grid = (B + TM - 1) / TM;
    fused_qh_kernel<<<grid, NTHREADS>>>(x, W1, b1, bn_g, bn_b, bn_m, bn_v,
                                        W2, b2, qw, W3, b3, out, B);
}

// round 7
// speedup vs baseline: 2.3073x; 2.3073x over previous
#include <cuda_runtime.h>
#include <cuda_bf16.h>
#include <math.h>
#include <stdint.h>

#define D_DIM 1280
#define TM 128
#define TN 64
#define KT 64
#define NTILES (D_DIM / KT)   // 20
#define NTHREADS 256

// ---- dynamic smem layout ----
// consts: S[64], T[64], b1[64], W2[4*64]  (floats)
#define OFF_S    0
#define OFF_T    256
#define OFF_B1   512
#define OFF_W2   768            // 1KB -> ends at 1792
#define OFF_XQ   2048           // xq buffer [128][4] floats (reuses stage, after sync)
#define OFF_STAGE 2048
#define STG_AH 0                // A hi  128x64 bf16 = 16KB
#define STG_AL 16384            // A lo  16KB
#define STG_BH 32768            // B hi  64x64 bf16 = 8KB
#define STG_BL 40960            // B lo  8KB
#define STAGE_SZ 49152
#define SMEM_TOTAL (OFF_STAGE + STAGE_SZ)   // 51200

#define SWZ(b) ((b) ^ (((b) >> 3) & 0x70))

static __device__ __forceinline__ uint32_t smem_u32(const void* p) {
    uint32_t a;
    asm("{ .reg .u64 t; cvta.to.shared.u64 t, %1; cvt.u32.u64 %0, t; }" : "=r"(a) : "l"(p));
    return a;
}
static __device__ __forceinline__ void ldsm_x4(uint32_t* r, uint32_t addr) {
    asm volatile("ldmatrix.sync.aligned.m8n8.x4.shared.b16 {%0,%1,%2,%3}, [%4];"
                 : "=r"(r[0]), "=r"(r[1]), "=r"(r[2]), "=r"(r[3]) : "r"(addr));
}
static __device__ __forceinline__ void mma_bf16(float* d, const uint32_t* a, uint32_t b0, uint32_t b1) {
    asm volatile("mma.sync.aligned.m16n8k16.row.col.f32.bf16.bf16.f32 "
                 "{%0,%1,%2,%3}, {%4,%5,%6,%7}, {%8,%9}, {%0,%1,%2,%3};"
                 : "+f"(d[0]), "+f"(d[1]), "+f"(d[2]), "+f"(d[3])
                 : "r"(a[0]), "r"(a[1]), "r"(a[2]), "r"(a[3]), "r"(b0), "r"(b1));
}
// fp32 -> bf16 hi + bf16 lo (residual), packed per float4
static __device__ __forceinline__ void split4(float4 v, uint2& hi, uint2& lo) {
    __nv_bfloat16 a = __float2bfloat16_rn(v.x), b = __float2bfloat16_rn(v.y);
    __nv_bfloat16 c = __float2bfloat16_rn(v.z), d = __float2bfloat16_rn(v.w);
    float rx = v.x - __bfloat162float(a), ry = v.y - __bfloat162float(b);
    float rz = v.z - __bfloat162float(c), rw = v.w - __bfloat162float(d);
    __nv_bfloat162 H0 = __halves2bfloat162(a, b), H1 = __halves2bfloat162(c, d);
    __nv_bfloat162 L0 = __floats2bfloat162_rn(rx, ry), L1 = __floats2bfloat162_rn(rz, rw);
    hi.x = *(uint32_t*)&H0; hi.y = *(uint32_t*)&H1;
    lo.x = *(uint32_t*)&L0; lo.y = *(uint32_t*)&L1;
}

extern __shared__ char sm[];

__global__ __launch_bounds__(NTHREADS, 2)
void fused_qh_mma(const float* __restrict__ x,
                  const float* __restrict__ W1,
                  const float* __restrict__ b1,
                  const float* __restrict__ bn_g,
                  const float* __restrict__ bn_b,
                  const float* __restrict__ bn_m,
                  const float* __restrict__ bn_v,
                  const float* __restrict__ W2,
                  const float* __restrict__ b2,
                  const float* __restrict__ qw,
                  const float* __restrict__ W3,
                  const float* __restrict__ b3,
                  float* __restrict__ out,
                  int B)
{
    const int tid = threadIdx.x;
    const int w = tid >> 5;
    const int lane = tid & 31;
    const int row0 = blockIdx.x * TM;
    const uint32_t smb = smem_u32(sm);

    // epilogue constants to smem
    if (tid < 64) {
        float S = bn_g[tid] * rsqrtf(bn_v[tid] + 1e-5f);
        *(float*)(sm + OFF_S + tid * 4) = S;
        *(float*)(sm + OFF_T + tid * 4) = bn_b[tid] - bn_m[tid] * S;
        *(float*)(sm + OFF_B1 + tid * 4) = b1[tid];
    }
    *(float*)(sm + OFF_W2 + tid * 4) = W2[tid];

    // ---- ldmatrix address bases (fixed per lane) ----
    // A frag (16x16): lane l -> row 16w + (l&15), kunit base (l>>4)
    const int a_row = 16 * w + (lane & 15);
    const uint32_t a_row128 = (uint32_t)a_row * 128;
    const int a_rs = a_row & 7;
    const int a_ku0 = lane >> 4;
    // B frag x4 (2 n-subtiles): i=l>>3; row = 16p + 8*(i>>1) + (l&7); kunit base i&1
    const int b_i = lane >> 3;
    const int b_rowb = 8 * (b_i >> 1) + (lane & 7);
    const int b_rs = lane & 7;
    const int b_ku0 = b_i & 1;

    float acc[8][4];
#pragma unroll
    for (int s = 0; s < 8; ++s)
#pragma unroll
        for (int j = 0; j < 4; ++j) acc[s][j] = 0.f;

    float4 xb[8], wb[4];
    // prologue: tile 0 (coords: f = tid + it*256, r = f>>4, kq = f&15 -> 8B units)
#pragma unroll
    for (int it = 0; it < 8; ++it) {
        int f = tid + it * NTHREADS, r = f >> 4, kq = f & 15;
        int gr = row0 + r;
        xb[it] = (gr < B) ? *(const float4*)(x + (size_t)gr * D_DIM + kq * 4)
                          : make_float4(0.f, 0.f, 0.f, 0.f);
    }
#pragma unroll
    for (int it = 0; it < 4; ++it) {
        int f = tid + it * NTHREADS, r = f >> 4, kq = f & 15;
        wb[it] = *(const float4*)(W1 + (size_t)r * D_DIM + kq * 4);
    }

    for (int t = 0; t < NTILES; ++t) {
        if (t) __syncthreads();   // prior tile's readers done before overwrite

        // commit prefetched regs -> split -> swizzled smem (bf16 hi/lo)
#pragma unroll
        for (int it = 0; it < 8; ++it) {
            int f = tid + it * NTHREADS, r = f >> 4, kq = f & 15;
            uint32_t sw = SWZ((uint32_t)(r * 128 + kq * 8));
            uint2 hi, lo; split4(xb[it], hi, lo);
            *(uint2*)(sm + OFF_STAGE + STG_AH + sw) = hi;
            *(uint2*)(sm + OFF_STAGE + STG_AL + sw) = lo;
        }
#pragma unroll
        for (int it = 0; it < 4; ++it) {
            int f = tid + it * NTHREADS, r = f >> 4, kq = f & 15;
            uint32_t sw = SWZ((uint32_t)(r * 128 + kq * 8));
            uint2 hi, lo; split4(wb[it], hi, lo);
            *(uint2*)(sm + OFF_STAGE + STG_BH + sw) = hi;
            *(uint2*)(sm + OFF_STAGE + STG_BL + sw) = lo;
        }
        __syncthreads();

        // prefetch next tile (overlaps with MMA below)
        if (t + 1 < NTILES) {
            const int kb = (t + 1) * KT;
#pragma unroll
            for (int it = 0; it < 8; ++it) {
                int f = tid + it * NTHREADS, r = f >> 4, kq = f & 15;
                int gr = row0 + r;
                xb[it] = (gr < B) ? *(const float4*)(x + (size_t)gr * D_DIM + kb + kq * 4)
                                  : make_float4(0.f, 0.f, 0.f, 0.f);
            }
#pragma unroll
            for (int it = 0; it < 4; ++it) {
                int f = tid + it * NTHREADS, r = f >> 4, kq = f & 15;
                wb[it] = *(const float4*)(W1 + (size_t)r * D_DIM + kb + kq * 4);
            }
        }

        // compute: 4 k16-steps x (A hi/lo ldsm + 4 B-pairs x (2 ldsm + 6 mma))
        const uint32_t sa = smb + OFF_STAGE;
#pragma unroll
        for (int kk = 0; kk < 4; ++kk) {
            uint32_t ah[4], al[4];
            int ku = 2 * kk + a_ku0;
            uint32_t aoff = a_row128 + (uint32_t)((ku ^ a_rs) << 4);
            ldsm_x4(ah, sa + STG_AH + aoff);
            ldsm_x4(al, sa + STG_AL + aoff);
#pragma unroll
            for (int p = 0; p < 4; ++p) {
                int kub = 2 * kk + b_ku0;
                uint32_t boff = (uint32_t)((16 * p + b_rowb) * 128) +
                                (uint32_t)((kub ^ b_rs) << 4);
                uint32_t bh[4], bl[4];
                ldsm_x4(bh, sa + STG_BH + boff);
                ldsm_x4(bl, sa + STG_BL + boff);
                // subtile 2p
                mma_bf16(acc[2 * p], ah, bh[0], bh[1]);
                mma_bf16(acc[2 * p], ah, bl[0], bl[1]);
                mma_bf16(acc[2 * p], al, bh[0], bh[1]);
                // subtile 2p+1
                mma_bf16(acc[2 * p + 1], ah, bh[2], bh[3]);
                mma_bf16(acc[2 * p + 1], ah, bl[2], bl[3]);
                mma_bf16(acc[2 * p + 1], al, bh[2], bh[3]);
            }
        }
    }

    // ---- epilogue: bias+relu+BN on fragments, W2 dot, quad-reduce ----
    const float* Ss  = (const float*)(sm + OFF_S);
    const float* Ts  = (const float*)(sm + OFF_T);
    const float* b1s = (const float*)(sm + OFF_B1);
    const float* w2s = (const float*)(sm + OFF_W2);
    float xqA[4] = {0.f, 0.f, 0.f, 0.f};   // row 16w + lane/4
    float xqB[4] = {0.f, 0.f, 0.f, 0.f};   // row 16w + lane/4 + 8
#pragma unroll
    for (int s = 0; s < 8; ++s) {
#pragma unroll
        for (int j = 0; j < 4; ++j) {
            int col = s * 8 + (lane & 3) * 2 + (j & 1);
            float hv = fmaxf(acc[s][j] + b1s[col], 0.f);
            float h = fmaf(hv, Ss[col], Ts[col]);
            float* xq = (j < 2) ? xqA : xqB;
            xq[0] = fmaf(h, w2s[col], xq[0]);
            xq[1] = fmaf(h, w2s[64 + col], xq[1]);
            xq[2] = fmaf(h, w2s[128 + col], xq[2]);
            xq[3] = fmaf(h, w2s[192 + col], xq[3]);
        }
    }
#pragma unroll
    for (int off = 1; off <= 2; off <<= 1) {
#pragma unroll
        for (int q = 0; q < 4; ++q) {
            xqA[q] += __shfl_xor_sync(0xFFFFFFFFu, xqA[q], off);
            xqB[q] += __shfl_xor_sync(0xFFFFFFFFu, xqB[q], off);
        }
    }
    __syncthreads();   // all warps done with stage smem before xq buffer reuse
    if ((lane & 3) == 0) {
        int r = 16 * w + (lane >> 2);
        float* xqb = (float*)(sm + OFF_XQ);
#pragma unroll
        for (int q = 0; q < 4; ++q) {
            xqb[r * 4 + q] = xqA[q];
            xqb[(r + 8) * 4 + q] = xqB[q];
        }
    }
    __syncthreads();

    // ---- per-row quantum circuit (validated path) ----
    if (tid < TM) {
        int row = row0 + tid;
        if (row < B) {
            const float* xqb = (const float*)(sm + OFF_XQ);
            float xq0 = xqb[tid * 4 + 0] + b2[0];
            float xq1 = xqb[tid * 4 + 1] + b2[1];
            float xq2 = xqb[tid * 4 + 2] + b2[2];
            float xq3 = xqb[tid * 4 + 3] + b2[3];
            float xq[4] = { tanhf(xq0), tanhf(xq1), tanhf(xq2), tanhf(xq3) };
            float cc[4], ss[4];
#pragma unroll
            for (int i = 0; i < 4; i++) {
                float a = tanhf(xq[i]) * 3.14159274101257324f;
                sincosf(0.5f * a, &ss[i], &cc[i]);
            }
            float re[16], im[16];
#pragma unroll
            for (int idx = 0; idx < 16; ++idx) {
                re[idx] = ((idx & 8) ? ss[0] : cc[0]) * ((idx & 4) ? ss[1] : cc[1]) *
                          ((idx & 2) ? ss[2] : cc[2]) * ((idx & 1) ? ss[3] : cc[3]);
                im[idx] = 0.f;
            }
#pragma unroll
            for (int l = 0; l < 2; l++) {
#pragma unroll
                for (int i = 0; i < 4; i++) {
                    float cy, sy, cz, sz;
                    sincosf(0.5f * qw[l * 8 + i * 2 + 0], &sy, &cy);
                    sincosf(0.5f * qw[l * 8 + i * 2 + 1], &sz, &cz);
                    int mask = 8 >> i;
#pragma unroll
                    for (int idx = 0; idx < 16; ++idx) {
                        if (idx & mask) continue;
                        int p = idx | mask;
                        float r0 = re[idx], i0 = im[idx], r1 = re[p], i1 = im[p];
                        float nr0 = cy * r0 - sy * r1, ni0 = cy * i0 - sy * i1;
                        float nr1 = sy * r0 + cy * r1, ni1 = sy * i0 + cy * i1;
                        re[idx] = fmaf(sz, ni0, cz * nr0);
                        im[idx] = fmaf(-sz, nr0, cz * ni0);
                        re[p]   = fmaf(-sz, ni1, cz * nr1);
                        im[p]   = fmaf(sz, nr1, cz * ni1);
                    }
                }
#pragma unroll
                for (int i = 0; i < 4; i++) {
                    int mc = 8 >> i, mt = 8 >> ((i + 1) & 3);
#pragma unroll
                    for (int idx = 0; idx < 16; ++idx) {
                        if ((idx & mc) && !(idx & mt)) {
                            int p = idx | mt;
                            float tq;
                            tq = re[idx]; re[idx] = re[p]; re[p] = tq;
                            tq = im[idx]; im[idx] = im[p]; im[p] = tq;
                        }
                    }
                }
            }
            float z0 = 0.f, z1 = 0.f, z2 = 0.f, z3 = 0.f;
#pragma unroll
            for (int idx = 0; idx < 16; ++idx) {
                float p = re[idx] * re[idx] + im[idx] * im[idx];
                z0 += (idx & 8) ? -p : p;
                z1 += (idx & 4) ? -p : p;
                z2 += (idx & 2) ? -p : p;
                z3 += (idx & 1) ? -p : p;
            }
#pragma unroll
            for (int c = 0; c < 10; c++) {
                float o = b3[c];
                o = fmaf(z0, W3[c * 4 + 0], o);
                o = fmaf(z1, W3[c * 4 + 1], o);
                o = fmaf(z2, W3[c * 4 + 2], o);
                o = fmaf(z3, W3[c * 4 + 3], o);
                out[(size_t)row * 10 + c] = o;
            }
        }
    }
}

extern "C" void kernel_launch(void* const* d_in, const int* in_sizes, int n_in,
                              void* d_out, int out_size)
{
    const float* x    = (const float*)d_in[0];
    const float* W1   = (const float*)d_in[1];
    const float* b1   = (const float*)d_in[2];
    const float* bn_g = (const float*)d_in[3];
    const float* bn_b = (const float*)d_in[4];
    const float* bn_m = (const float*)d_in[5];
    const float* bn_v = (const float*)d_in[6];
    const float* W2   = (const float*)d_in[7];
    const float* b2   = (const float*)d_in[8];
    const float* qw   = (const float*)d_in[9];
    const float* W3   = (const float*)d_in[10];
    const float* b3   = (const float*)d_in[11];
    float* out = (float*)d_out;

    int B = in_sizes[0] / D_DIM;
    int grid = (B + TM - 1) / TM;
    cudaFuncSetAttribute(fused_qh_mma, cudaFuncAttributeMaxDynamicSharedMemorySize, SMEM_TOTAL);
    fused_qh_mma<<<grid, NTHREADS, SMEM_TOTAL>>>(x, W1, b1, bn_g, bn_b, bn_m, bn_v,
                                                 W2, b2, qw, W3, b3, out, B);
}